// round 16
// baseline (speedup 1.0000x reference)
#include <cuda_runtime.h>
#include <math.h>
#include <stdint.h>

// Problem dims
#define BB 2
#define SSEQ 2048
#define EE 1024
#define HH 16
#define DD 64
#define MMROWS (BB * SSEQ)  // 4096

// Scratch (device globals: allocation-free)
__device__ float g_Q[BB * HH * SSEQ * DD];
__device__ float g_K[BB * HH * SSEQ * DD];
__device__ float g_V[BB * HH * DD * SSEQ];  // TRANSPOSED: [b,h,d,s]
__device__ float g_attn[BB * SSEQ * EE];
// pre-rounded tf32 copies
__device__ float g_Aq[MMROWS * EE];
__device__ float g_Ak[MMROWS * EE];
__device__ float g_Av[MMROWS * EE];
__device__ float g_Wq[EE * EE];
__device__ float g_Wk[EE * EE];
__device__ float g_Wv[EE * EE];
__device__ float g_Wo[EE * EE];

// ---------------------------------------------------------------------------
// helpers
// ---------------------------------------------------------------------------
__device__ __forceinline__ float f2tf(float x) {
    uint32_t r;
    asm("cvt.rna.tf32.f32 %0, %1;" : "=r"(r) : "f"(x));
    return __uint_as_float(r);
}

__device__ __forceinline__ void mma_tf32(float& c0, float& c1, float& c2, float& c3,
                                         uint32_t a0, uint32_t a1, uint32_t a2, uint32_t a3,
                                         uint32_t b0, uint32_t b1) {
    asm volatile(
        "mma.sync.aligned.m16n8k8.row.col.f32.tf32.tf32.f32 "
        "{%0,%1,%2,%3}, {%4,%5,%6,%7}, {%8,%9}, {%0,%1,%2,%3};\n"
        : "+f"(c0), "+f"(c1), "+f"(c2), "+f"(c3)
        : "r"(a0), "r"(a1), "r"(a2), "r"(a3), "r"(b0), "r"(b1));
}

__device__ __forceinline__ void cpa16(uint32_t dst, const void* src) {
    asm volatile("cp.async.cg.shared.global [%0], [%1], 16;\n" :: "r"(dst), "l"(src));
}
__device__ __forceinline__ void cpa_commit() {
    asm volatile("cp.async.commit_group;\n");
}
__device__ __forceinline__ void cpa_wait_all() {
    asm volatile("cp.async.wait_group 0;\n");
}

// tail-aware wait for a 4-stage ring with 3 groups in flight at steady state
__device__ __forceinline__ void ring_wait(int s, int nsteps) {
    if (s < nsteps - 2)       asm volatile("cp.async.wait_group 2;" ::: "memory");
    else if (s == nsteps - 2) asm volatile("cp.async.wait_group 1;" ::: "memory");
    else                      asm volatile("cp.async.wait_group 0;" ::: "memory");
}

// ---------------------------------------------------------------------------
// preround: tf32-round inputs and weights once (memory-bound).
// ---------------------------------------------------------------------------
#define N_IN4 (MMROWS * EE / 4)   // 1048576
#define N_W4 (EE * EE / 4)        // 262144
#define N_TOT4 (3 * N_IN4 + 4 * N_W4)

__global__ __launch_bounds__(256) void preround(
    const float* __restrict__ q, const float* __restrict__ k, const float* __restrict__ v,
    const float* __restrict__ wq, const float* __restrict__ wk,
    const float* __restrict__ wv, const float* __restrict__ wo) {
    int i = blockIdx.x * blockDim.x + threadIdx.x;
    if (i >= N_TOT4) return;
    const float* src;
    float* dst;
    int off;
    if (i < N_IN4)            { src = q;  dst = g_Aq; off = i; }
    else if (i < 2 * N_IN4)   { src = k;  dst = g_Ak; off = i - N_IN4; }
    else if (i < 3 * N_IN4)   { src = v;  dst = g_Av; off = i - 2 * N_IN4; }
    else if (i < 3 * N_IN4 + N_W4)     { src = wq; dst = g_Wq; off = i - 3 * N_IN4; }
    else if (i < 3 * N_IN4 + 2 * N_W4) { src = wk; dst = g_Wk; off = i - 3 * N_IN4 - N_W4; }
    else if (i < 3 * N_IN4 + 3 * N_W4) { src = wv; dst = g_Wv; off = i - 3 * N_IN4 - 2 * N_W4; }
    else                               { src = wo; dst = g_Wo; off = i - 3 * N_IN4 - 3 * N_W4; }
    float4 x = ((const float4*)src)[off];
    ((float4*)dst)[off] = make_float4(f2tf(x.x), f2tf(x.y), f2tf(x.z), f2tf(x.w));
}

// ---------------------------------------------------------------------------
#define GPD 20
#define ASZ (128 * GPD)
#define BSZ (128 * GPD)
#define GEMM_SMEM ((4 * ASZ + 4 * BSZ) * (int)sizeof(float))  // 80 KB (4-stage)

// ---------------------------------------------------------------------------
// GEMM core A: 256 thr, 8 warps of 64x32, CTA 128x128, BK=16, 4-stage
// cp.async ring. MODE 0/1/2: QKV scatter (+RoPE for 0,1; V transposed).
// ---------------------------------------------------------------------------
template <int MODE>
__device__ __forceinline__ void gemm_core8(const float* __restrict__ A,
                                           const float* __restrict__ W,
                                           const float* __restrict__ bias,
                                           float* __restrict__ dst,
                                           const float* invf,
                                           float* As, float* Bs) {
    const int tid = threadIdx.x;
    const int n0 = blockIdx.x * 128;
    const int m0 = blockIdx.y * 128;
    const int wid = tid >> 5;
    const int lane = tid & 31;
    const int g = lane >> 2;
    const int t4 = lane & 3;
    const int mw = (wid & 1) * 64;
    const int nw = (wid >> 1) * 32;

    const int sr = tid >> 2;
    const int skq = (tid & 3) * 4;

    const uint32_t as_u32 = (uint32_t)__cvta_generic_to_shared(As);
    const uint32_t bs_u32 = (uint32_t)__cvta_generic_to_shared(Bs);

    float acc[4][4][4];
#pragma unroll
    for (int mt = 0; mt < 4; mt++)
#pragma unroll
        for (int nt = 0; nt < 4; nt++)
#pragma unroll
            for (int qq = 0; qq < 4; qq++) acc[mt][nt][qq] = 0.f;

    const int nsteps = EE / 16;  // 64

    auto stage = [&](int st) {
        const int buf = st & 3;
        const int k0 = st * 16;
        const uint32_t ab = as_u32 + buf * ASZ * 4;
        const uint32_t bb = bs_u32 + buf * BSZ * 4;
        cpa16(ab + (sr * GPD + skq) * 4,        &A[(size_t)(m0 + sr) * EE + k0 + skq]);
        cpa16(ab + ((sr + 64) * GPD + skq) * 4, &A[(size_t)(m0 + sr + 64) * EE + k0 + skq]);
        cpa16(bb + (sr * GPD + skq) * 4,        &W[(size_t)(n0 + sr) * EE + k0 + skq]);
        cpa16(bb + ((sr + 64) * GPD + skq) * 4, &W[(size_t)(n0 + sr + 64) * EE + k0 + skq]);
        cpa_commit();
    };

    stage(0); stage(1); stage(2);

    for (int s = 0; s < nsteps; s++) {
        ring_wait(s, nsteps);
        __syncthreads();
        if (s + 3 < nsteps) stage(s + 3);

        const int cur = s & 3;
        const float* Ac = As + cur * ASZ;
        const float* Bc = Bs + cur * BSZ;

#pragma unroll
        for (int kk = 0; kk < 16; kk += 8) {
            uint32_t af[4][4];
#pragma unroll
            for (int mt = 0; mt < 4; mt++) {
                int m = mw + mt * 16 + g;
                af[mt][0] = __float_as_uint(Ac[m * GPD + kk + t4]);
                af[mt][1] = __float_as_uint(Ac[(m + 8) * GPD + kk + t4]);
                af[mt][2] = __float_as_uint(Ac[m * GPD + kk + t4 + 4]);
                af[mt][3] = __float_as_uint(Ac[(m + 8) * GPD + kk + t4 + 4]);
            }
            uint32_t bf[4][2];
#pragma unroll
            for (int nt = 0; nt < 4; nt++) {
                int n = nw + nt * 8 + g;
                bf[nt][0] = __float_as_uint(Bc[n * GPD + kk + t4]);
                bf[nt][1] = __float_as_uint(Bc[n * GPD + kk + t4 + 4]);
            }
#pragma unroll
            for (int mt = 0; mt < 4; mt++)
#pragma unroll
                for (int nt = 0; nt < 4; nt++)
                    mma_tf32(acc[mt][nt][0], acc[mt][nt][1], acc[mt][nt][2], acc[mt][nt][3],
                             af[mt][0], af[mt][1], af[mt][2], af[mt][3],
                             bf[nt][0], bf[nt][1]);
        }
    }

#pragma unroll
    for (int mt = 0; mt < 4; mt++) {
        int gm0 = m0 + mw + mt * 16 + g;
        int gm1 = gm0 + 8;
        int s0 = gm0 & (SSEQ - 1), s1 = gm1 & (SSEQ - 1);
        int bb0 = gm0 >> 11, bb1 = gm1 >> 11;
#pragma unroll
        for (int nt = 0; nt < 4; nt++) {
            int gn = n0 + nw + nt * 8 + 2 * t4;
            float bv0 = bias[gn], bv1 = bias[gn + 1];
            float e00 = acc[mt][nt][0] + bv0, e01 = acc[mt][nt][1] + bv1;
            float e10 = acc[mt][nt][2] + bv0, e11 = acc[mt][nt][3] + bv1;
            int h = gn >> 6, d0 = gn & 63;
            if (MODE < 2) {  // RoPE on Q, K
                float if0 = invf[d0 & 31], if1 = invf[(d0 + 1) & 31];
                float sa, ca, sb, cb;
                sincosf((float)s0 * if0, &sa, &ca);
                sincosf((float)s0 * if1, &sb, &cb);
                float y00 = e00 * ca - e01 * sa;
                float y01 = e01 * cb + e00 * sb;
                sincosf((float)s1 * if0, &sa, &ca);
                sincosf((float)s1 * if1, &sb, &cb);
                float y10 = e10 * ca - e11 * sa;
                float y11 = e11 * cb + e10 * sb;
                e00 = y00; e01 = y01; e10 = y10; e11 = y11;
            }
            e00 = f2tf(e00); e01 = f2tf(e01); e10 = f2tf(e10); e11 = f2tf(e11);
            if (MODE < 2) {
                *(float2*)&dst[(((size_t)(bb0 * HH + h)) * SSEQ + s0) * DD + d0] = make_float2(e00, e01);
                *(float2*)&dst[(((size_t)(bb1 * HH + h)) * SSEQ + s1) * DD + d0] = make_float2(e10, e11);
            } else {
                // V transposed: [b,h,d,s]
                size_t vb = ((size_t)(bb0 * HH + h)) * DD;
                dst[(vb + d0) * SSEQ + s0]     = e00;
                dst[(vb + d0 + 1) * SSEQ + s0] = e01;
                size_t vb1 = ((size_t)(bb1 * HH + h)) * DD;
                dst[(vb1 + d0) * SSEQ + s1]     = e10;
                dst[(vb1 + d0 + 1) * SSEQ + s1] = e11;
            }
        }
    }
}

// ---------------------------------------------------------------------------
// GEMM core B (gemm_out): 128 thr, 4 warps of 64x64, 4-stage cp.async ring.
// ---------------------------------------------------------------------------
__device__ __forceinline__ void gemm_core4_out(const float* __restrict__ A,
                                               const float* __restrict__ W,
                                               const float* __restrict__ bias,
                                               float* __restrict__ dst,
                                               float* As, float* Bs) {
    const int tid = threadIdx.x;
    const int n0 = blockIdx.x * 128;
    const int m0 = blockIdx.y * 128;
    const int wid = tid >> 5;
    const int lane = tid & 31;
    const int g = lane >> 2;
    const int t4 = lane & 3;
    const int mw = (wid & 1) * 64;
    const int nw = (wid >> 1) * 64;

    const int sr = tid >> 2;          // 0..31
    const int skq = (tid & 3) * 4;

    const uint32_t as_u32 = (uint32_t)__cvta_generic_to_shared(As);
    const uint32_t bs_u32 = (uint32_t)__cvta_generic_to_shared(Bs);

    float acc[4][8][4];
#pragma unroll
    for (int mt = 0; mt < 4; mt++)
#pragma unroll
        for (int nt = 0; nt < 8; nt++)
#pragma unroll
            for (int qq = 0; qq < 4; qq++) acc[mt][nt][qq] = 0.f;

    const int nsteps = EE / 16;

    auto stage = [&](int st) {
        const int buf = st & 3;
        const int k0 = st * 16;
        const uint32_t ab = as_u32 + buf * ASZ * 4;
        const uint32_t bb = bs_u32 + buf * BSZ * 4;
#pragma unroll
        for (int p = 0; p < 4; p++) {
            cpa16(ab + ((sr + 32 * p) * GPD + skq) * 4, &A[(size_t)(m0 + sr + 32 * p) * EE + k0 + skq]);
            cpa16(bb + ((sr + 32 * p) * GPD + skq) * 4, &W[(size_t)(n0 + sr + 32 * p) * EE + k0 + skq]);
        }
        cpa_commit();
    };

    stage(0); stage(1); stage(2);

    for (int s = 0; s < nsteps; s++) {
        ring_wait(s, nsteps);
        __syncthreads();
        if (s + 3 < nsteps) stage(s + 3);

        const int cur = s & 3;
        const float* Ac = As + cur * ASZ;
        const float* Bc = Bs + cur * BSZ;

#pragma unroll
        for (int kk = 0; kk < 16; kk += 8) {
            uint32_t af[4][4];
#pragma unroll
            for (int mt = 0; mt < 4; mt++) {
                int m = mw + mt * 16 + g;
                af[mt][0] = __float_as_uint(Ac[m * GPD + kk + t4]);
                af[mt][1] = __float_as_uint(Ac[(m + 8) * GPD + kk + t4]);
                af[mt][2] = __float_as_uint(Ac[m * GPD + kk + t4 + 4]);
                af[mt][3] = __float_as_uint(Ac[(m + 8) * GPD + kk + t4 + 4]);
            }
            uint32_t bf[8][2];
#pragma unroll
            for (int nt = 0; nt < 8; nt++) {
                int n = nw + nt * 8 + g;
                bf[nt][0] = __float_as_uint(Bc[n * GPD + kk + t4]);
                bf[nt][1] = __float_as_uint(Bc[n * GPD + kk + t4 + 4]);
            }
#pragma unroll
            for (int mt = 0; mt < 4; mt++)
#pragma unroll
                for (int nt = 0; nt < 8; nt++)
                    mma_tf32(acc[mt][nt][0], acc[mt][nt][1], acc[mt][nt][2], acc[mt][nt][3],
                             af[mt][0], af[mt][1], af[mt][2], af[mt][3],
                             bf[nt][0], bf[nt][1]);
        }
    }

#pragma unroll
    for (int mt = 0; mt < 4; mt++) {
        int gm0 = m0 + mw + mt * 16 + g;
        int gm1 = gm0 + 8;
#pragma unroll
        for (int nt = 0; nt < 8; nt++) {
            int gn = n0 + nw + nt * 8 + 2 * t4;
            float bv0 = bias[gn], bv1 = bias[gn + 1];
            *(float2*)&dst[(size_t)gm0 * EE + gn] = make_float2(acc[mt][nt][0] + bv0, acc[mt][nt][1] + bv1);
            *(float2*)&dst[(size_t)gm1 * EE + gn] = make_float2(acc[mt][nt][2] + bv0, acc[mt][nt][3] + bv1);
        }
    }
}

__global__ __launch_bounds__(256) void gemm_qkv(
    const float* __restrict__ bq, const float* __restrict__ bk,
    const float* __restrict__ bv) {
    extern __shared__ __align__(16) float smg[];
    __shared__ float invf[32];
    if (threadIdx.x < 32)
        invf[threadIdx.x] = (float)exp(-(double)threadIdx.x * (9.210340371976184 / 32.0));

    const int z = blockIdx.z;
    float* As = smg;
    float* Bs = smg + 4 * ASZ;
    if (z == 0)      gemm_core8<0>(g_Aq, g_Wq, bq, g_Q, invf, As, Bs);
    else if (z == 1) gemm_core8<1>(g_Ak, g_Wk, bk, g_K, invf, As, Bs);
    else             gemm_core8<2>(g_Av, g_Wv, bv, g_V, invf, As, Bs);
}

__global__ __launch_bounds__(128) void gemm_out(const float* __restrict__ bias,
                                                float* __restrict__ Cout) {
    extern __shared__ __align__(16) float smg[];
    gemm_core4_out(g_attn, g_Wo, bias, Cout, smg, smg + 4 * ASZ);
}

// ---------------------------------------------------------------------------
// Flash attention v3 (unchanged from R14 best): Q tile 256 (8 warps x 32
// q-rows), shared B-fragments, tf32 mma, cp.async double-buffered K/V,
// V transposed [d][s], warp-private Ss + __syncwarp.
// ---------------------------------------------------------------------------
#define ALD 68
#define QTT 256
#define NTILE (SSEQ / 64)  // 32

__global__ __launch_bounds__(256, 1) void attn_tc(const int* __restrict__ mask) {
    extern __shared__ __align__(16) float smx[];
    float* Kb[2] = {smx, smx + 64 * ALD};
    float* Vb[2] = {smx + 2 * 64 * ALD, smx + 3 * 64 * ALD};  // [d][s_local]
    float* Ss = smx + 4 * 64 * ALD;                 // [256][68], warp-private rows
    int* msk = (int*)(smx + 4 * 64 * ALD + QTT * ALD);  // [2][64]

    const int tid = threadIdx.x;
    const int wid = tid >> 5;
    const int lane = tid & 31;
    const int g = lane >> 2;
    const int t4 = lane & 3;
    const int qw = wid * 32;

    const int bh = blockIdx.y;
    const int q0 = blockIdx.x * QTT;
    const int b = bh / HH;
    const int h = bh - b * HH;
    const size_t base = (size_t)bh * SSEQ * DD;
    const size_t basev = (size_t)bh * DD * SSEQ;

    const uint32_t smem_u32 = (uint32_t)__cvta_generic_to_shared(smx);
    const uint32_t kb_u32[2] = {smem_u32, smem_u32 + 64 * ALD * 4};
    const uint32_t vb_u32[2] = {smem_u32 + 2 * 64 * ALD * 4, smem_u32 + 3 * 64 * ALD * 4};
    const uint32_t msk_u32 = smem_u32 + (4 * 64 * ALD + QTT * ALD) * 4;

    uint32_t aq[2][8][4];
#pragma unroll
    for (int m2 = 0; m2 < 2; m2++) {
        const float* qr0 = &g_Q[base + (size_t)(q0 + qw + m2 * 16 + g) * DD];
        const float* qr1 = qr0 + 8 * DD;
#pragma unroll
        for (int kk8 = 0; kk8 < 8; kk8++) {
            aq[m2][kk8][0] = __float_as_uint(qr0[kk8 * 8 + t4]);
            aq[m2][kk8][1] = __float_as_uint(qr1[kk8 * 8 + t4]);
            aq[m2][kk8][2] = __float_as_uint(qr0[kk8 * 8 + t4 + 4]);
            aq[m2][kk8][3] = __float_as_uint(qr1[kk8 * 8 + t4 + 4]);
        }
    }

    float o[2][8][4];
#pragma unroll
    for (int m2 = 0; m2 < 2; m2++)
#pragma unroll
        for (int nt = 0; nt < 8; nt++)
#pragma unroll
            for (int qq = 0; qq < 4; qq++) o[m2][nt][qq] = 0.f;
    float mr[2][2] = {{-INFINITY, -INFINITY}, {-INFINITY, -INFINITY}};
    float lr[2][2] = {{0.f, 0.f}, {0.f, 0.f}};

    {
#pragma unroll
        for (int u = 0; u < 4; u++) {
            int n = tid + 256 * u;
            int r = n >> 4, c = (n & 15) * 4;
            cpa16(kb_u32[0] + (r * ALD + c) * 4, &g_K[base + (size_t)r * DD + c]);
            cpa16(vb_u32[0] + (r * ALD + c) * 4, &g_V[basev + (size_t)r * SSEQ + c]);
        }
        if (tid < 16) cpa16(msk_u32 + tid * 16, &mask[b * SSEQ + tid * 4]);
        cpa_commit();
    }

    for (int kt = 0; kt < NTILE; kt++) {
        cpa_wait_all();
        __syncthreads();

        const int cur = kt & 1;
        if (kt + 1 < NTILE) {
            const int k0 = (kt + 1) * 64;
            const int nb = cur ^ 1;
#pragma unroll
            for (int u = 0; u < 4; u++) {
                int n = tid + 256 * u;
                int r = n >> 4, c = (n & 15) * 4;
                cpa16(kb_u32[nb] + (r * ALD + c) * 4, &g_K[base + (size_t)(k0 + r) * DD + c]);
                cpa16(vb_u32[nb] + (r * ALD + c) * 4, &g_V[basev + (size_t)r * SSEQ + k0 + c]);
            }
            if (tid < 16) cpa16(msk_u32 + 256 * nb + tid * 16, &mask[b * SSEQ + k0 + tid * 4]);
            cpa_commit();
        }

        const float* Kc = Kb[cur];
        const float* Vc = Vb[cur];
        const int* mc = msk + 64 * cur;

        float s[2][8][4];
#pragma unroll
        for (int m2 = 0; m2 < 2; m2++)
#pragma unroll
            for (int nt = 0; nt < 8; nt++)
#pragma unroll
                for (int qq = 0; qq < 4; qq++) s[m2][nt][qq] = 0.f;
#pragma unroll
        for (int kk8 = 0; kk8 < 8; kk8++) {
            int kk = kk8 * 8;
#pragma unroll
            for (int nt = 0; nt < 8; nt++) {
                uint32_t b0 = __float_as_uint(Kc[(nt * 8 + g) * ALD + kk + t4]);
                uint32_t b1 = __float_as_uint(Kc[(nt * 8 + g) * ALD + kk + t4 + 4]);
                mma_tf32(s[0][nt][0], s[0][nt][1], s[0][nt][2], s[0][nt][3],
                         aq[0][kk8][0], aq[0][kk8][1], aq[0][kk8][2], aq[0][kk8][3], b0, b1);
                mma_tf32(s[1][nt][0], s[1][nt][1], s[1][nt][2], s[1][nt][3],
                         aq[1][kk8][0], aq[1][kk8][1], aq[1][kk8][2], aq[1][kk8][3], b0, b1);
            }
        }

#pragma unroll
        for (int m2 = 0; m2 < 2; m2++) {
#pragma unroll
            for (int nt = 0; nt < 8; nt++) {
                int mka = mc[nt * 8 + 2 * t4];
                int mkb = mc[nt * 8 + 2 * t4 + 1];
                s[m2][nt][0] = mka ? s[m2][nt][0] * 0.125f : -1e30f;
                s[m2][nt][1] = mkb ? s[m2][nt][1] * 0.125f : -1e30f;
                s[m2][nt][2] = mka ? s[m2][nt][2] * 0.125f : -1e30f;
                s[m2][nt][3] = mkb ? s[m2][nt][3] * 0.125f : -1e30f;
            }
            float m0 = -INFINITY, m1 = -INFINITY;
#pragma unroll
            for (int nt = 0; nt < 8; nt++) {
                m0 = fmaxf(m0, fmaxf(s[m2][nt][0], s[m2][nt][1]));
                m1 = fmaxf(m1, fmaxf(s[m2][nt][2], s[m2][nt][3]));
            }
#pragma unroll
            for (int off = 1; off <= 2; off <<= 1) {
                m0 = fmaxf(m0, __shfl_xor_sync(0xffffffffu, m0, off));
                m1 = fmaxf(m1, __shfl_xor_sync(0xffffffffu, m1, off));
            }
            float mn0 = fmaxf(mr[m2][0], m0), mn1 = fmaxf(mr[m2][1], m1);
            float al0 = __expf(mr[m2][0] - mn0), al1 = __expf(mr[m2][1] - mn1);
            float ls0 = 0.f, ls1 = 0.f;
#pragma unroll
            for (int nt = 0; nt < 8; nt++) {
                s[m2][nt][0] = __expf(s[m2][nt][0] - mn0);
                s[m2][nt][1] = __expf(s[m2][nt][1] - mn0);
                s[m2][nt][2] = __expf(s[m2][nt][2] - mn1);
                s[m2][nt][3] = __expf(s[m2][nt][3] - mn1);
                ls0 += s[m2][nt][0] + s[m2][nt][1];
                ls1 += s[m2][nt][2] + s[m2][nt][3];
            }
#pragma unroll
            for (int off = 1; off <= 2; off <<= 1) {
                ls0 += __shfl_xor_sync(0xffffffffu, ls0, off);
                ls1 += __shfl_xor_sync(0xffffffffu, ls1, off);
            }
            mr[m2][0] = mn0; mr[m2][1] = mn1;
            lr[m2][0] = lr[m2][0] * al0 + ls0;
            lr[m2][1] = lr[m2][1] * al1 + ls1;
#pragma unroll
            for (int nt = 0; nt < 8; nt++) {
                o[m2][nt][0] *= al0; o[m2][nt][1] *= al0;
                o[m2][nt][2] *= al1; o[m2][nt][3] *= al1;
            }
            int r0 = qw + m2 * 16 + g;
#pragma unroll
            for (int nt = 0; nt < 8; nt++) {
                *(float2*)&Ss[r0 * ALD + nt * 8 + 2 * t4] =
                    make_float2(f2tf(s[m2][nt][0]), f2tf(s[m2][nt][1]));
                *(float2*)&Ss[(r0 + 8) * ALD + nt * 8 + 2 * t4] =
                    make_float2(f2tf(s[m2][nt][2]), f2tf(s[m2][nt][3]));
            }
        }
        __syncwarp();

#pragma unroll
        for (int kk8 = 0; kk8 < 8; kk8++) {
            int kk = kk8 * 8;
            uint32_t pa[2][4];
#pragma unroll
            for (int m2 = 0; m2 < 2; m2++) {
                int r0 = qw + m2 * 16 + g;
                pa[m2][0] = __float_as_uint(Ss[r0 * ALD + kk + t4]);
                pa[m2][1] = __float_as_uint(Ss[(r0 + 8) * ALD + kk + t4]);
                pa[m2][2] = __float_as_uint(Ss[r0 * ALD + kk + t4 + 4]);
                pa[m2][3] = __float_as_uint(Ss[(r0 + 8) * ALD + kk + t4 + 4]);
            }
#pragma unroll
            for (int nt = 0; nt < 8; nt++) {
                uint32_t b0 = __float_as_uint(Vc[(nt * 8 + g) * ALD + kk + t4]);
                uint32_t b1 = __float_as_uint(Vc[(nt * 8 + g) * ALD + kk + t4 + 4]);
                mma_tf32(o[0][nt][0], o[0][nt][1], o[0][nt][2], o[0][nt][3],
                         pa[0][0], pa[0][1], pa[0][2], pa[0][3], b0, b1);
                mma_tf32(o[1][nt][0], o[1][nt][1], o[1][nt][2], o[1][nt][3],
                         pa[1][0], pa[1][1], pa[1][2], pa[1][3], b0, b1);
            }
        }
    }

#pragma unroll
    for (int m2 = 0; m2 < 2; m2++) {
        float inv0 = 1.f / lr[m2][0], inv1 = 1.f / lr[m2][1];
        int row0 = q0 + qw + m2 * 16 + g, row1 = row0 + 8;
#pragma unroll
        for (int nt = 0; nt < 8; nt++) {
            int col = h * DD + nt * 8 + 2 * t4;
            *(float2*)&g_attn[((size_t)b * SSEQ + row0) * EE + col] =
                make_float2(f2tf(o[m2][nt][0] * inv0), f2tf(o[m2][nt][1] * inv0));
            *(float2*)&g_attn[((size_t)b * SSEQ + row1) * EE + col] =
                make_float2(f2tf(o[m2][nt][2] * inv1), f2tf(o[m2][nt][3] * inv1));
        }
    }
}

// ---------------------------------------------------------------------------
extern "C" void kernel_launch(void* const* d_in, const int* in_sizes, int n_in,
                              void* d_out, int out_size) {
    const float* query = (const float*)d_in[0];
    const float* key   = (const float*)d_in[1];
    const float* value = (const float*)d_in[2];
    const int*   mask  = (const int*)d_in[3];
    const float* Wq = (const float*)d_in[4];
    const float* bq = (const float*)d_in[5];
    const float* Wk = (const float*)d_in[6];
    const float* bk = (const float*)d_in[7];
    const float* Wv = (const float*)d_in[8];
    const float* bv = (const float*)d_in[9];
    const float* Wo = (const float*)d_in[10];
    const float* bo = (const float*)d_in[11];
    float* out = (float*)d_out;

    const int attn_smem = (4 * 64 * ALD + QTT * ALD) * (int)sizeof(float) + 2 * 64 * (int)sizeof(int);
    static bool attr_set = false;
    if (!attr_set) {
        cudaFuncSetAttribute(attn_tc, cudaFuncAttributeMaxDynamicSharedMemorySize, attn_smem);
        cudaFuncSetAttribute(gemm_qkv, cudaFuncAttributeMaxDynamicSharedMemorySize, GEMM_SMEM);
        cudaFuncSetAttribute(gemm_out, cudaFuncAttributeMaxDynamicSharedMemorySize, GEMM_SMEM);
        attr_set = true;
    }

    preround<<<(N_TOT4 + 255) / 256, 256>>>(query, key, value, Wq, Wk, Wv, Wo);

    dim3 qkv_grid(EE / 128, MMROWS / 128, 3);  // (8, 32, 3)
    gemm_qkv<<<qkv_grid, 256, GEMM_SMEM>>>(bq, bk, bv);

    attn_tc<<<dim3(SSEQ / QTT, BB * HH), 256, attn_smem>>>(mask);

    gemm_out<<<dim3(EE / 128, MMROWS / 128), 128, GEMM_SMEM>>>(bo, out);
}

// round 17
// speedup vs baseline: 1.0650x; 1.0650x over previous
#include <cuda_runtime.h>
#include <math.h>
#include <stdint.h>

// Problem dims
#define BB 2
#define SSEQ 2048
#define EE 1024
#define HH 16
#define DD 64
#define MMROWS (BB * SSEQ)  // 4096

// Scratch (device globals: allocation-free)
__device__ float g_Q[BB * HH * SSEQ * DD];
__device__ float g_K[BB * HH * SSEQ * DD];
__device__ float g_V[BB * HH * DD * SSEQ];  // TRANSPOSED: [b,h,d,s]
__device__ float g_attn[BB * SSEQ * EE];
// pre-rounded tf32 copies
__device__ float g_Aq[MMROWS * EE];
__device__ float g_Ak[MMROWS * EE];
__device__ float g_Av[MMROWS * EE];
__device__ float g_Wq[EE * EE];
__device__ float g_Wk[EE * EE];
__device__ float g_Wv[EE * EE];
__device__ float g_Wo[EE * EE];

// ---------------------------------------------------------------------------
// helpers
// ---------------------------------------------------------------------------
__device__ __forceinline__ float f2tf(float x) {
    uint32_t r;
    asm("cvt.rna.tf32.f32 %0, %1;" : "=r"(r) : "f"(x));
    return __uint_as_float(r);
}

__device__ __forceinline__ void mma_tf32(float& c0, float& c1, float& c2, float& c3,
                                         uint32_t a0, uint32_t a1, uint32_t a2, uint32_t a3,
                                         uint32_t b0, uint32_t b1) {
    asm volatile(
        "mma.sync.aligned.m16n8k8.row.col.f32.tf32.tf32.f32 "
        "{%0,%1,%2,%3}, {%4,%5,%6,%7}, {%8,%9}, {%0,%1,%2,%3};\n"
        : "+f"(c0), "+f"(c1), "+f"(c2), "+f"(c3)
        : "r"(a0), "r"(a1), "r"(a2), "r"(a3), "r"(b0), "r"(b1));
}

__device__ __forceinline__ void cpa16(uint32_t dst, const void* src) {
    asm volatile("cp.async.cg.shared.global [%0], [%1], 16;\n" :: "r"(dst), "l"(src));
}
__device__ __forceinline__ void cpa_commit() {
    asm volatile("cp.async.commit_group;\n");
}
__device__ __forceinline__ void cpa_wait_all() {
    asm volatile("cp.async.wait_group 0;\n");
}

// tail-aware wait for a 4-stage ring with 3 groups in flight at steady state
__device__ __forceinline__ void ring_wait(int s, int nsteps) {
    if (s < nsteps - 2)       asm volatile("cp.async.wait_group 2;" ::: "memory");
    else if (s == nsteps - 2) asm volatile("cp.async.wait_group 1;" ::: "memory");
    else                      asm volatile("cp.async.wait_group 0;" ::: "memory");
}

// ---------------------------------------------------------------------------
// preround: tf32-round inputs and weights once (memory-bound).
// ---------------------------------------------------------------------------
#define N_IN4 (MMROWS * EE / 4)   // 1048576
#define N_W4 (EE * EE / 4)        // 262144
#define N_TOT4 (3 * N_IN4 + 4 * N_W4)

__global__ __launch_bounds__(256) void preround(
    const float* __restrict__ q, const float* __restrict__ k, const float* __restrict__ v,
    const float* __restrict__ wq, const float* __restrict__ wk,
    const float* __restrict__ wv, const float* __restrict__ wo) {
    int i = blockIdx.x * blockDim.x + threadIdx.x;
    if (i >= N_TOT4) return;
    const float* src;
    float* dst;
    int off;
    if (i < N_IN4)            { src = q;  dst = g_Aq; off = i; }
    else if (i < 2 * N_IN4)   { src = k;  dst = g_Ak; off = i - N_IN4; }
    else if (i < 3 * N_IN4)   { src = v;  dst = g_Av; off = i - 2 * N_IN4; }
    else if (i < 3 * N_IN4 + N_W4)     { src = wq; dst = g_Wq; off = i - 3 * N_IN4; }
    else if (i < 3 * N_IN4 + 2 * N_W4) { src = wk; dst = g_Wk; off = i - 3 * N_IN4 - N_W4; }
    else if (i < 3 * N_IN4 + 3 * N_W4) { src = wv; dst = g_Wv; off = i - 3 * N_IN4 - 2 * N_W4; }
    else                               { src = wo; dst = g_Wo; off = i - 3 * N_IN4 - 3 * N_W4; }
    float4 x = ((const float4*)src)[off];
    ((float4*)dst)[off] = make_float4(f2tf(x.x), f2tf(x.y), f2tf(x.z), f2tf(x.w));
}

// ---------------------------------------------------------------------------
#define GPD 20
#define ASZ (128 * GPD)
#define BSZ (128 * GPD)
#define GEMM_SMEM ((4 * ASZ + 4 * BSZ) * (int)sizeof(float))  // 80 KB (4-stage)

// ---------------------------------------------------------------------------
// GEMM core A: 256 thr, 8 warps of 64x32, CTA 128x128, BK=16, 4-stage ring.
// MODE 0/1/2: QKV scatter (+RoPE for 0,1; V transposed).
// ---------------------------------------------------------------------------
template <int MODE>
__device__ __forceinline__ void gemm_core8(const float* __restrict__ A,
                                           const float* __restrict__ W,
                                           const float* __restrict__ bias,
                                           float* __restrict__ dst,
                                           const float* invf,
                                           float* As, float* Bs) {
    const int tid = threadIdx.x;
    const int n0 = blockIdx.x * 128;
    const int m0 = blockIdx.y * 128;
    const int wid = tid >> 5;
    const int lane = tid & 31;
    const int g = lane >> 2;
    const int t4 = lane & 3;
    const int mw = (wid & 1) * 64;
    const int nw = (wid >> 1) * 32;

    const int sr = tid >> 2;
    const int skq = (tid & 3) * 4;

    const uint32_t as_u32 = (uint32_t)__cvta_generic_to_shared(As);
    const uint32_t bs_u32 = (uint32_t)__cvta_generic_to_shared(Bs);

    float acc[4][4][4];
#pragma unroll
    for (int mt = 0; mt < 4; mt++)
#pragma unroll
        for (int nt = 0; nt < 4; nt++)
#pragma unroll
            for (int qq = 0; qq < 4; qq++) acc[mt][nt][qq] = 0.f;

    const int nsteps = EE / 16;  // 64

    auto stage = [&](int st) {
        const int buf = st & 3;
        const int k0 = st * 16;
        const uint32_t ab = as_u32 + buf * ASZ * 4;
        const uint32_t bb = bs_u32 + buf * BSZ * 4;
        cpa16(ab + (sr * GPD + skq) * 4,        &A[(size_t)(m0 + sr) * EE + k0 + skq]);
        cpa16(ab + ((sr + 64) * GPD + skq) * 4, &A[(size_t)(m0 + sr + 64) * EE + k0 + skq]);
        cpa16(bb + (sr * GPD + skq) * 4,        &W[(size_t)(n0 + sr) * EE + k0 + skq]);
        cpa16(bb + ((sr + 64) * GPD + skq) * 4, &W[(size_t)(n0 + sr + 64) * EE + k0 + skq]);
        cpa_commit();
    };

    stage(0); stage(1); stage(2);

    for (int s = 0; s < nsteps; s++) {
        ring_wait(s, nsteps);
        __syncthreads();
        if (s + 3 < nsteps) stage(s + 3);

        const int cur = s & 3;
        const float* Ac = As + cur * ASZ;
        const float* Bc = Bs + cur * BSZ;

#pragma unroll
        for (int kk = 0; kk < 16; kk += 8) {
            uint32_t af[4][4];
#pragma unroll
            for (int mt = 0; mt < 4; mt++) {
                int m = mw + mt * 16 + g;
                af[mt][0] = __float_as_uint(Ac[m * GPD + kk + t4]);
                af[mt][1] = __float_as_uint(Ac[(m + 8) * GPD + kk + t4]);
                af[mt][2] = __float_as_uint(Ac[m * GPD + kk + t4 + 4]);
                af[mt][3] = __float_as_uint(Ac[(m + 8) * GPD + kk + t4 + 4]);
            }
            uint32_t bf[4][2];
#pragma unroll
            for (int nt = 0; nt < 4; nt++) {
                int n = nw + nt * 8 + g;
                bf[nt][0] = __float_as_uint(Bc[n * GPD + kk + t4]);
                bf[nt][1] = __float_as_uint(Bc[n * GPD + kk + t4 + 4]);
            }
#pragma unroll
            for (int mt = 0; mt < 4; mt++)
#pragma unroll
                for (int nt = 0; nt < 4; nt++)
                    mma_tf32(acc[mt][nt][0], acc[mt][nt][1], acc[mt][nt][2], acc[mt][nt][3],
                             af[mt][0], af[mt][1], af[mt][2], af[mt][3],
                             bf[nt][0], bf[nt][1]);
        }
    }

#pragma unroll
    for (int mt = 0; mt < 4; mt++) {
        int gm0 = m0 + mw + mt * 16 + g;
        int gm1 = gm0 + 8;
        int s0 = gm0 & (SSEQ - 1), s1 = gm1 & (SSEQ - 1);
        int bb0 = gm0 >> 11, bb1 = gm1 >> 11;
#pragma unroll
        for (int nt = 0; nt < 4; nt++) {
            int gn = n0 + nw + nt * 8 + 2 * t4;
            float bv0 = bias[gn], bv1 = bias[gn + 1];
            float e00 = acc[mt][nt][0] + bv0, e01 = acc[mt][nt][1] + bv1;
            float e10 = acc[mt][nt][2] + bv0, e11 = acc[mt][nt][3] + bv1;
            int h = gn >> 6, d0 = gn & 63;
            if (MODE < 2) {  // RoPE on Q, K
                float if0 = invf[d0 & 31], if1 = invf[(d0 + 1) & 31];
                float sa, ca, sb, cb;
                sincosf((float)s0 * if0, &sa, &ca);
                sincosf((float)s0 * if1, &sb, &cb);
                float y00 = e00 * ca - e01 * sa;
                float y01 = e01 * cb + e00 * sb;
                sincosf((float)s1 * if0, &sa, &ca);
                sincosf((float)s1 * if1, &sb, &cb);
                float y10 = e10 * ca - e11 * sa;
                float y11 = e11 * cb + e10 * sb;
                e00 = y00; e01 = y01; e10 = y10; e11 = y11;
            }
            e00 = f2tf(e00); e01 = f2tf(e01); e10 = f2tf(e10); e11 = f2tf(e11);
            if (MODE < 2) {
                *(float2*)&dst[(((size_t)(bb0 * HH + h)) * SSEQ + s0) * DD + d0] = make_float2(e00, e01);
                *(float2*)&dst[(((size_t)(bb1 * HH + h)) * SSEQ + s1) * DD + d0] = make_float2(e10, e11);
            } else {
                // V transposed: [b,h,d,s]
                size_t vb = ((size_t)(bb0 * HH + h)) * DD;
                dst[(vb + d0) * SSEQ + s0]     = e00;
                dst[(vb + d0 + 1) * SSEQ + s0] = e01;
                size_t vb1 = ((size_t)(bb1 * HH + h)) * DD;
                dst[(vb1 + d0) * SSEQ + s1]     = e10;
                dst[(vb1 + d0 + 1) * SSEQ + s1] = e11;
            }
        }
    }
}

// ---------------------------------------------------------------------------
// GEMM core B (gemm_out): 128 thr, 4 warps of 64x64, 4-stage cp.async ring.
// ---------------------------------------------------------------------------
__device__ __forceinline__ void gemm_core4_out(const float* __restrict__ A,
                                               const float* __restrict__ W,
                                               const float* __restrict__ bias,
                                               float* __restrict__ dst,
                                               float* As, float* Bs) {
    const int tid = threadIdx.x;
    const int n0 = blockIdx.x * 128;
    const int m0 = blockIdx.y * 128;
    const int wid = tid >> 5;
    const int lane = tid & 31;
    const int g = lane >> 2;
    const int t4 = lane & 3;
    const int mw = (wid & 1) * 64;
    const int nw = (wid >> 1) * 64;

    const int sr = tid >> 2;
    const int skq = (tid & 3) * 4;

    const uint32_t as_u32 = (uint32_t)__cvta_generic_to_shared(As);
    const uint32_t bs_u32 = (uint32_t)__cvta_generic_to_shared(Bs);

    float acc[4][8][4];
#pragma unroll
    for (int mt = 0; mt < 4; mt++)
#pragma unroll
        for (int nt = 0; nt < 8; nt++)
#pragma unroll
            for (int qq = 0; qq < 4; qq++) acc[mt][nt][qq] = 0.f;

    const int nsteps = EE / 16;

    auto stage = [&](int st) {
        const int buf = st & 3;
        const int k0 = st * 16;
        const uint32_t ab = as_u32 + buf * ASZ * 4;
        const uint32_t bb = bs_u32 + buf * BSZ * 4;
#pragma unroll
        for (int p = 0; p < 4; p++) {
            cpa16(ab + ((sr + 32 * p) * GPD + skq) * 4, &A[(size_t)(m0 + sr + 32 * p) * EE + k0 + skq]);
            cpa16(bb + ((sr + 32 * p) * GPD + skq) * 4, &W[(size_t)(n0 + sr + 32 * p) * EE + k0 + skq]);
        }
        cpa_commit();
    };

    stage(0); stage(1); stage(2);

    for (int s = 0; s < nsteps; s++) {
        ring_wait(s, nsteps);
        __syncthreads();
        if (s + 3 < nsteps) stage(s + 3);

        const int cur = s & 3;
        const float* Ac = As + cur * ASZ;
        const float* Bc = Bs + cur * BSZ;

#pragma unroll
        for (int kk = 0; kk < 16; kk += 8) {
            uint32_t af[4][4];
#pragma unroll
            for (int mt = 0; mt < 4; mt++) {
                int m = mw + mt * 16 + g;
                af[mt][0] = __float_as_uint(Ac[m * GPD + kk + t4]);
                af[mt][1] = __float_as_uint(Ac[(m + 8) * GPD + kk + t4]);
                af[mt][2] = __float_as_uint(Ac[m * GPD + kk + t4 + 4]);
                af[mt][3] = __float_as_uint(Ac[(m + 8) * GPD + kk + t4 + 4]);
            }
            uint32_t bf[8][2];
#pragma unroll
            for (int nt = 0; nt < 8; nt++) {
                int n = nw + nt * 8 + g;
                bf[nt][0] = __float_as_uint(Bc[n * GPD + kk + t4]);
                bf[nt][1] = __float_as_uint(Bc[n * GPD + kk + t4 + 4]);
            }
#pragma unroll
            for (int mt = 0; mt < 4; mt++)
#pragma unroll
                for (int nt = 0; nt < 8; nt++)
                    mma_tf32(acc[mt][nt][0], acc[mt][nt][1], acc[mt][nt][2], acc[mt][nt][3],
                             af[mt][0], af[mt][1], af[mt][2], af[mt][3],
                             bf[nt][0], bf[nt][1]);
        }
    }

#pragma unroll
    for (int mt = 0; mt < 4; mt++) {
        int gm0 = m0 + mw + mt * 16 + g;
        int gm1 = gm0 + 8;
#pragma unroll
        for (int nt = 0; nt < 8; nt++) {
            int gn = n0 + nw + nt * 8 + 2 * t4;
            float bv0 = bias[gn], bv1 = bias[gn + 1];
            *(float2*)&dst[(size_t)gm0 * EE + gn] = make_float2(acc[mt][nt][0] + bv0, acc[mt][nt][1] + bv1);
            *(float2*)&dst[(size_t)gm1 * EE + gn] = make_float2(acc[mt][nt][2] + bv0, acc[mt][nt][3] + bv1);
        }
    }
}

__global__ __launch_bounds__(256) void gemm_qkv(
    const float* __restrict__ bq, const float* __restrict__ bk,
    const float* __restrict__ bv) {
    extern __shared__ __align__(16) float smg[];
    __shared__ float invf[32];
    if (threadIdx.x < 32)
        invf[threadIdx.x] = (float)exp(-(double)threadIdx.x * (9.210340371976184 / 32.0));

    const int z = blockIdx.z;
    float* As = smg;
    float* Bs = smg + 4 * ASZ;
    if (z == 0)      gemm_core8<0>(g_Aq, g_Wq, bq, g_Q, invf, As, Bs);
    else if (z == 1) gemm_core8<1>(g_Ak, g_Wk, bk, g_K, invf, As, Bs);
    else             gemm_core8<2>(g_Av, g_Wv, bv, g_V, invf, As, Bs);
}

__global__ __launch_bounds__(128) void gemm_out(const float* __restrict__ bias,
                                                float* __restrict__ Cout) {
    extern __shared__ __align__(16) float smg[];
    gemm_core4_out(g_attn, g_Wo, bias, Cout, smg, smg + 4 * ASZ);
}

// ---------------------------------------------------------------------------
// Flash attention v4: Q tile 256 (8 warps x 32 q-rows), shared B-fragments,
// 3-stage K/V cp.async ring (prefetch depth 2), deferred l-sum reduction
// (per-lane partials, reduced once at the end), warp-private Ss + __syncwarp.
// ---------------------------------------------------------------------------
#define ALD 68
#define QTT 256
#define NTILE (SSEQ / 64)  // 32
#define KVSZ (64 * ALD)

__global__ __launch_bounds__(256, 1) void attn_tc(const int* __restrict__ mask) {
    extern __shared__ __align__(16) float smx[];
    // layout: K[3] | V[3] | Ss | msk[3]
    float* Kb = smx;                        // 3 * KVSZ
    float* Vb = smx + 3 * KVSZ;             // 3 * KVSZ  [d][s_local]
    float* Ss = smx + 6 * KVSZ;             // [256][68], warp-private rows
    int* msk = (int*)(smx + 6 * KVSZ + QTT * ALD);  // [3][64]

    const int tid = threadIdx.x;
    const int wid = tid >> 5;
    const int lane = tid & 31;
    const int g = lane >> 2;
    const int t4 = lane & 3;
    const int qw = wid * 32;

    const int bh = blockIdx.y;
    const int q0 = blockIdx.x * QTT;
    const int b = bh / HH;
    const int h = bh - b * HH;
    const size_t base = (size_t)bh * SSEQ * DD;
    const size_t basev = (size_t)bh * DD * SSEQ;

    const uint32_t smem_u32 = (uint32_t)__cvta_generic_to_shared(smx);
    const uint32_t kb_u32 = smem_u32;
    const uint32_t vb_u32 = smem_u32 + 3 * KVSZ * 4;
    const uint32_t msk_u32 = smem_u32 + (6 * KVSZ + QTT * ALD) * 4;

    uint32_t aq[2][8][4];
#pragma unroll
    for (int m2 = 0; m2 < 2; m2++) {
        const float* qr0 = &g_Q[base + (size_t)(q0 + qw + m2 * 16 + g) * DD];
        const float* qr1 = qr0 + 8 * DD;
#pragma unroll
        for (int kk8 = 0; kk8 < 8; kk8++) {
            aq[m2][kk8][0] = __float_as_uint(qr0[kk8 * 8 + t4]);
            aq[m2][kk8][1] = __float_as_uint(qr1[kk8 * 8 + t4]);
            aq[m2][kk8][2] = __float_as_uint(qr0[kk8 * 8 + t4 + 4]);
            aq[m2][kk8][3] = __float_as_uint(qr1[kk8 * 8 + t4 + 4]);
        }
    }

    float o[2][8][4];
#pragma unroll
    for (int m2 = 0; m2 < 2; m2++)
#pragma unroll
        for (int nt = 0; nt < 8; nt++)
#pragma unroll
            for (int qq = 0; qq < 4; qq++) o[m2][nt][qq] = 0.f;
    float mr[2][2] = {{-INFINITY, -INFINITY}, {-INFINITY, -INFINITY}};
    float lr[2][2] = {{0.f, 0.f}, {0.f, 0.f}};  // per-lane partial sums

    auto stage = [&](int t) {
        const int buf = t - (t / 3) * 3;   // t % 3
        const int k0 = t * 64;
#pragma unroll
        for (int u = 0; u < 4; u++) {
            int n = tid + 256 * u;
            int r = n >> 4, c = (n & 15) * 4;
            cpa16(kb_u32 + (buf * KVSZ + r * ALD + c) * 4, &g_K[base + (size_t)(k0 + r) * DD + c]);
            cpa16(vb_u32 + (buf * KVSZ + r * ALD + c) * 4, &g_V[basev + (size_t)r * SSEQ + k0 + c]);
        }
        if (tid < 16) cpa16(msk_u32 + buf * 256 + tid * 16, &mask[b * SSEQ + k0 + tid * 4]);
        cpa_commit();
    };

    stage(0); stage(1);

    for (int kt = 0; kt < NTILE; kt++) {
        if (kt < NTILE - 1) asm volatile("cp.async.wait_group 1;" ::: "memory");
        else                asm volatile("cp.async.wait_group 0;" ::: "memory");
        __syncthreads();
        if (kt + 2 < NTILE) stage(kt + 2);

        const int cur = kt - (kt / 3) * 3;  // kt % 3
        const float* Kc = Kb + cur * KVSZ;
        const float* Vc = Vb + cur * KVSZ;
        const int* mc = msk + 64 * cur;

        float s[2][8][4];
#pragma unroll
        for (int m2 = 0; m2 < 2; m2++)
#pragma unroll
            for (int nt = 0; nt < 8; nt++)
#pragma unroll
                for (int qq = 0; qq < 4; qq++) s[m2][nt][qq] = 0.f;
#pragma unroll
        for (int kk8 = 0; kk8 < 8; kk8++) {
            int kk = kk8 * 8;
#pragma unroll
            for (int nt = 0; nt < 8; nt++) {
                uint32_t b0 = __float_as_uint(Kc[(nt * 8 + g) * ALD + kk + t4]);
                uint32_t b1 = __float_as_uint(Kc[(nt * 8 + g) * ALD + kk + t4 + 4]);
                mma_tf32(s[0][nt][0], s[0][nt][1], s[0][nt][2], s[0][nt][3],
                         aq[0][kk8][0], aq[0][kk8][1], aq[0][kk8][2], aq[0][kk8][3], b0, b1);
                mma_tf32(s[1][nt][0], s[1][nt][1], s[1][nt][2], s[1][nt][3],
                         aq[1][kk8][0], aq[1][kk8][1], aq[1][kk8][2], aq[1][kk8][3], b0, b1);
            }
        }

#pragma unroll
        for (int m2 = 0; m2 < 2; m2++) {
#pragma unroll
            for (int nt = 0; nt < 8; nt++) {
                int mka = mc[nt * 8 + 2 * t4];
                int mkb = mc[nt * 8 + 2 * t4 + 1];
                s[m2][nt][0] = mka ? s[m2][nt][0] * 0.125f : -1e30f;
                s[m2][nt][1] = mkb ? s[m2][nt][1] * 0.125f : -1e30f;
                s[m2][nt][2] = mka ? s[m2][nt][2] * 0.125f : -1e30f;
                s[m2][nt][3] = mkb ? s[m2][nt][3] * 0.125f : -1e30f;
            }
            float m0 = -INFINITY, m1 = -INFINITY;
#pragma unroll
            for (int nt = 0; nt < 8; nt++) {
                m0 = fmaxf(m0, fmaxf(s[m2][nt][0], s[m2][nt][1]));
                m1 = fmaxf(m1, fmaxf(s[m2][nt][2], s[m2][nt][3]));
            }
#pragma unroll
            for (int off = 1; off <= 2; off <<= 1) {
                m0 = fmaxf(m0, __shfl_xor_sync(0xffffffffu, m0, off));
                m1 = fmaxf(m1, __shfl_xor_sync(0xffffffffu, m1, off));
            }
            float mn0 = fmaxf(mr[m2][0], m0), mn1 = fmaxf(mr[m2][1], m1);
            float al0 = __expf(mr[m2][0] - mn0), al1 = __expf(mr[m2][1] - mn1);
            float ls0 = 0.f, ls1 = 0.f;
#pragma unroll
            for (int nt = 0; nt < 8; nt++) {
                s[m2][nt][0] = __expf(s[m2][nt][0] - mn0);
                s[m2][nt][1] = __expf(s[m2][nt][1] - mn0);
                s[m2][nt][2] = __expf(s[m2][nt][2] - mn1);
                s[m2][nt][3] = __expf(s[m2][nt][3] - mn1);
                ls0 += s[m2][nt][0] + s[m2][nt][1];
                ls1 += s[m2][nt][2] + s[m2][nt][3];
            }
            // deferred: lr stays per-lane partial (al identical across lanes)
            mr[m2][0] = mn0; mr[m2][1] = mn1;
            lr[m2][0] = lr[m2][0] * al0 + ls0;
            lr[m2][1] = lr[m2][1] * al1 + ls1;
#pragma unroll
            for (int nt = 0; nt < 8; nt++) {
                o[m2][nt][0] *= al0; o[m2][nt][1] *= al0;
                o[m2][nt][2] *= al1; o[m2][nt][3] *= al1;
            }
            int r0 = qw + m2 * 16 + g;
#pragma unroll
            for (int nt = 0; nt < 8; nt++) {
                *(float2*)&Ss[r0 * ALD + nt * 8 + 2 * t4] =
                    make_float2(f2tf(s[m2][nt][0]), f2tf(s[m2][nt][1]));
                *(float2*)&Ss[(r0 + 8) * ALD + nt * 8 + 2 * t4] =
                    make_float2(f2tf(s[m2][nt][2]), f2tf(s[m2][nt][3]));
            }
        }
        __syncwarp();

#pragma unroll
        for (int kk8 = 0; kk8 < 8; kk8++) {
            int kk = kk8 * 8;
            uint32_t pa[2][4];
#pragma unroll
            for (int m2 = 0; m2 < 2; m2++) {
                int r0 = qw + m2 * 16 + g;
                pa[m2][0] = __float_as_uint(Ss[r0 * ALD + kk + t4]);
                pa[m2][1] = __float_as_uint(Ss[(r0 + 8) * ALD + kk + t4]);
                pa[m2][2] = __float_as_uint(Ss[r0 * ALD + kk + t4 + 4]);
                pa[m2][3] = __float_as_uint(Ss[(r0 + 8) * ALD + kk + t4 + 4]);
            }
#pragma unroll
            for (int nt = 0; nt < 8; nt++) {
                uint32_t b0 = __float_as_uint(Vc[(nt * 8 + g) * ALD + kk + t4]);
                uint32_t b1 = __float_as_uint(Vc[(nt * 8 + g) * ALD + kk + t4 + 4]);
                mma_tf32(o[0][nt][0], o[0][nt][1], o[0][nt][2], o[0][nt][3],
                         pa[0][0], pa[0][1], pa[0][2], pa[0][3], b0, b1);
                mma_tf32(o[1][nt][0], o[1][nt][1], o[1][nt][2], o[1][nt][3],
                         pa[1][0], pa[1][1], pa[1][2], pa[1][3], b0, b1);
            }
        }
    }

    // final l reduction across the 4-lane group, then normalize + store
#pragma unroll
    for (int m2 = 0; m2 < 2; m2++) {
#pragma unroll
        for (int off = 1; off <= 2; off <<= 1) {
            lr[m2][0] += __shfl_xor_sync(0xffffffffu, lr[m2][0], off);
            lr[m2][1] += __shfl_xor_sync(0xffffffffu, lr[m2][1], off);
        }
        float inv0 = 1.f / lr[m2][0], inv1 = 1.f / lr[m2][1];
        int row0 = q0 + qw + m2 * 16 + g, row1 = row0 + 8;
#pragma unroll
        for (int nt = 0; nt < 8; nt++) {
            int col = h * DD + nt * 8 + 2 * t4;
            *(float2*)&g_attn[((size_t)b * SSEQ + row0) * EE + col] =
                make_float2(f2tf(o[m2][nt][0] * inv0), f2tf(o[m2][nt][1] * inv0));
            *(float2*)&g_attn[((size_t)b * SSEQ + row1) * EE + col] =
                make_float2(f2tf(o[m2][nt][2] * inv1), f2tf(o[m2][nt][3] * inv1));
        }
    }
}

// ---------------------------------------------------------------------------
extern "C" void kernel_launch(void* const* d_in, const int* in_sizes, int n_in,
                              void* d_out, int out_size) {
    const float* query = (const float*)d_in[0];
    const float* key   = (const float*)d_in[1];
    const float* value = (const float*)d_in[2];
    const int*   mask  = (const int*)d_in[3];
    const float* Wq = (const float*)d_in[4];
    const float* bq = (const float*)d_in[5];
    const float* Wk = (const float*)d_in[6];
    const float* bk = (const float*)d_in[7];
    const float* Wv = (const float*)d_in[8];
    const float* bv = (const float*)d_in[9];
    const float* Wo = (const float*)d_in[10];
    const float* bo = (const float*)d_in[11];
    float* out = (float*)d_out;

    const int attn_smem = (6 * KVSZ + QTT * ALD) * (int)sizeof(float) + 3 * 64 * (int)sizeof(int);
    static bool attr_set = false;
    if (!attr_set) {
        cudaFuncSetAttribute(attn_tc, cudaFuncAttributeMaxDynamicSharedMemorySize, attn_smem);
        cudaFuncSetAttribute(gemm_qkv, cudaFuncAttributeMaxDynamicSharedMemorySize, GEMM_SMEM);
        cudaFuncSetAttribute(gemm_out, cudaFuncAttributeMaxDynamicSharedMemorySize, GEMM_SMEM);
        attr_set = true;
    }

    preround<<<(N_TOT4 + 255) / 256, 256>>>(query, key, value, Wq, Wk, Wv, Wo);

    dim3 qkv_grid(EE / 128, MMROWS / 128, 3);  // (8, 32, 3)
    gemm_qkv<<<qkv_grid, 256, GEMM_SMEM>>>(bq, bk, bv);

    attn_tc<<<dim3(SSEQ / QTT, BB * HH), 256, attn_smem>>>(mask);

    gemm_out<<<dim3(EE / 128, MMROWS / 128), 128, GEMM_SMEM>>>(bo, out);
}